// round 15
// baseline (speedup 1.0000x reference)
#include <cuda_runtime.h>
#include <math.h>

#define KCODES   8192
#define DIM      256
#define NTOK     8192       // B*H*W
#define HWSZ     1024
#define ZQ_ELEMS 2097152
#define OUT_FULL (ZQ_ELEMS + 2 + NTOK)
#define CAP      16         // candidates stored per token (overflow -> full rescan)
#define NPART    16         // |z|^2 partials per token

static __device__ float    g_zn2p[NPART * NTOK]; // per-token |z|^2 partials
static __device__ float    g_w2[KCODES];
static __device__ unsigned g_wmax2_bits;         // monotone max, idempotent across replays
static __device__ int      g_idx[NTOK];
static __device__ int      g_hist[KCODES];
static __device__ double   g_loss;
static __device__ unsigned g_done;
static __device__ int      g_mc_cnt;             // multi-candidate worklist size
static __device__ int      g_mc_tok[NTOK];       // packed (cnt<<16) | token
static __device__ int      g_cand[NTOK * CAP];   // candidate code ids per token
static __device__ float    g_cg[NTOK * CAP];     // candidate gumbel values per token

// ==== Kernel A: |z|^2 partials (coalesced over NCHW) + |w|^2 + zeroing =======
__global__ void __launch_bounds__(256) k_prep(const float* __restrict__ ze,
                                              const float* __restrict__ w) {
    int blk = blockIdx.x, t = threadIdx.x;
    if (blk < 512) {
        // |z|^2 partial over a 16-d chunk for 256 hw positions; fully coalesced, MLP=16
        int b   = blk >> 6;
        int rem = blk & 63;
        int hwc = rem >> 4;          // 4 hw chunks of 256
        int dc  = rem & 15;          // 16 d chunks of 16
        int hw  = (hwc << 8) + t;
        const float* p = ze + (size_t)(b * DIM + dc * 16) * HWSZ + hw;
        float acc = 0.f;
#pragma unroll
        for (int d = 0; d < 16; d++) {
            float v = __ldg(p + (size_t)d * HWSZ);
            acc += v * v;
        }
        g_zn2p[dc * NTOK + (b << 10) + hw] = acc;
    } else if (blk < 1536) {
        // |w_k|^2 (one warp per row) + block-reduced global max (1 atomic/block)
        __shared__ float wm[8];
        int lane = t & 31, wrp = t >> 5;
        int row  = ((blk - 512) << 3) | wrp;
        const float4* p = (const float4*)(w + (size_t)row * DIM);
        float s = 0.f;
#pragma unroll
        for (int j = 0; j < 2; j++) {
            float4 v = __ldg(p + lane * 2 + j);
            s += v.x * v.x + v.y * v.y + v.z * v.z + v.w * v.w;
        }
#pragma unroll
        for (int o = 16; o; o >>= 1) s += __shfl_xor_sync(0xffffffffu, s, o);
        if (lane == 0) { g_w2[row] = s; wm[wrp] = s; }
        __syncthreads();
        if (t == 0) {
            float mx = wm[0];
#pragma unroll
            for (int q = 1; q < 8; q++) mx = fmaxf(mx, wm[q]);
            atomicMax(&g_wmax2_bits, __float_as_uint(mx));
        }
    } else {
        int i = ((blk - 1536) << 8) | t;
        g_hist[i] = 0;
        if (i == 0) { g_loss = 0.0; g_done = 0u; g_mc_cnt = 0; }
    }
}

// == Kernel B (lean): stream max + selective re-read + collect; defer cnt>1 ===
__global__ void __launch_bounds__(256, 8) k_argmax(const float* __restrict__ gum,
                                                   float* __restrict__ out,
                                                   int write_extras) {
    const int n = blockIdx.x;
    const int t = threadIdx.x;
    const int lane = t & 31, wrp = t >> 5;
    __shared__ float sh_p[NPART];
    __shared__ float sh_red[8];
    __shared__ int   sh_cand[CAP];
    __shared__ float sh_cg[CAP];
    __shared__ int   sh_cnt;

    if (t < NPART) sh_p[t] = g_zn2p[t * NTOK + n];   // |z|^2 partials
    if (t == 0) sh_cnt = 0;

    // ---- single streaming pass: per-thread running max only (values dead) ----
    const float4* row4 = (const float4*)(gum + (size_t)n * KCODES);
    float mt = -INFINITY;
#pragma unroll
    for (int j = 0; j < 8; j++) {
        float4 v = __ldcs(row4 + t + j * 256);
        mt = fmaxf(mt, fmaxf(fmaxf(v.x, v.y), fmaxf(v.z, v.w)));
    }
    float m = mt;
#pragma unroll
    for (int o = 16; o; o >>= 1) m = fmaxf(m, __shfl_xor_sync(0xffffffffu, m, o));
    if (lane == 0) sh_red[wrp] = m;
    __syncthreads();
    float gmax = sh_red[0];
#pragma unroll
    for (int i = 1; i < 8; i++) gmax = fmaxf(gmax, sh_red[i]);
    float zn2 = 0.f;
#pragma unroll
    for (int i = 0; i < NPART; i++) zn2 += sh_p[i];
    float wmax2  = __uint_as_float(g_wmax2_bits);
    float thresh = gmax - (4.f * sqrtf(zn2) * sqrtf(wmax2) + wmax2 + 1e-5f);

    // ---- selective re-read: only threads whose local max clears the bar ----
    if (mt >= thresh) {
#pragma unroll
        for (int j = 0; j < 8; j++) {
            float4 v = __ldg(row4 + t + j * 256);
            int kb = (t + j * 256) << 2;
            if (v.x >= thresh) { int p = atomicAdd(&sh_cnt, 1); if (p < CAP) { sh_cand[p] = kb;     sh_cg[p] = v.x; } }
            if (v.y >= thresh) { int p = atomicAdd(&sh_cnt, 1); if (p < CAP) { sh_cand[p] = kb + 1; sh_cg[p] = v.y; } }
            if (v.z >= thresh) { int p = atomicAdd(&sh_cnt, 1); if (p < CAP) { sh_cand[p] = kb + 2; sh_cg[p] = v.z; } }
            if (v.w >= thresh) { int p = atomicAdd(&sh_cnt, 1); if (p < CAP) { sh_cand[p] = kb + 3; sh_cg[p] = v.w; } }
        }
    }
    __syncthreads();
    int cnt = sh_cnt;

    if (cnt == 1) {
        if (t == 0) {
            int k = sh_cand[0];                      // ~87% of tokens: resolved inline
            g_idx[n] = k;
            atomicAdd(&g_hist[k], 1);
            if (write_extras) out[ZQ_ELEMS + 2 + n] = (float)k;
        }
    } else {
        // defer to k_resolve: push token + its candidates (if they fit)
        __shared__ int s_pos;
        if (t == 0) s_pos = atomicAdd(&g_mc_cnt, 1);
        __syncthreads();
        int pos = s_pos;
        if (t == 0) g_mc_tok[pos] = (min(cnt, 0xFFFF) << 16) | n;
        if (t < CAP && t < cnt) {
            g_cand[n * CAP + t] = sh_cand[t];
            g_cg[n * CAP + t]   = sh_cg[t];
        }
    }
}

// == Kernel B2: resolve multi-candidate tokens (~13%), exact fp32 scoring =====
__global__ void __launch_bounds__(256) k_resolve(const float* __restrict__ gum,
                                                 const float* __restrict__ ze,
                                                 const float* __restrict__ w,
                                                 float* __restrict__ out,
                                                 int write_extras) {
    const int t = threadIdx.x;
    const int lane = t & 31, wrp = t >> 5;
    __shared__ float sh_z[DIM];
    __shared__ float sh_bv[8];
    __shared__ int   sh_bk[8];
    __shared__ float sh_vs[256];
    __shared__ int   sh_ks[256];

    int total = g_mc_cnt;
    for (int it = blockIdx.x; it < total; it += gridDim.x) {
        int packed = g_mc_tok[it];
        int n   = packed & 0xFFFF;
        int cnt = (unsigned)packed >> 16;
        int b = n >> 10, hw = n & (HWSZ - 1);

        __syncthreads();   // guard sh_z reuse across iterations
        sh_z[t] = __ldg(&ze[(size_t)(b * DIM + t) * HWSZ + hw]);
        __syncthreads();

        int best_k = -1;
        if (cnt <= CAP) {
            // warp-parallel exact scoring: warp handles candidates wrp, wrp+8, ...
            float bv = -INFINITY; int bk = KCODES;
            for (int c = wrp; c < cnt; c += 8) {
                int k = g_cand[n * CAP + c];
                const float4* wr = (const float4*)(w + (size_t)k * DIM);
                float dot = 0.f;
#pragma unroll
                for (int j = 0; j < 2; j++) {
                    float4 a = __ldg(wr + lane * 2 + j);
                    int db = lane * 8 + j * 4;
                    dot += a.x * sh_z[db] + a.y * sh_z[db + 1] + a.z * sh_z[db + 2] + a.w * sh_z[db + 3];
                }
#pragma unroll
                for (int o = 16; o; o >>= 1) dot += __shfl_xor_sync(0xffffffffu, dot, o);
                float sc = g_cg[n * CAP + c] + 2.f * dot - g_w2[k];
                if (sc > bv || (sc == bv && k < bk)) { bv = sc; bk = k; }
            }
            if (lane == 0) { sh_bv[wrp] = bv; sh_bk[wrp] = bk; }
            __syncthreads();
            if (t == 0) {
                float fb = -INFINITY; int fk = KCODES;
#pragma unroll
                for (int i = 0; i < 8; i++) {
                    float v = sh_bv[i]; int k = sh_bk[i];
                    if (v > fb || (v == fb && k < fk)) { fb = v; fk = k; }
                }
                best_k = fk;
            }
        } else {
            // statistically unreachable safety net: exact full scan
            float bs = -INFINITY; int bk = KCODES;
            for (int k = t; k < KCODES; k += 256) {
                float dot = 0.f;
                for (int d = 0; d < DIM; d++) dot += sh_z[d] * w[(size_t)k * DIM + d];
                float sc = __ldg(&gum[(size_t)n * KCODES + k]) + 2.f * dot - g_w2[k];
                if (sc > bs || (sc == bs && k < bk)) { bs = sc; bk = k; }
            }
            sh_vs[t] = bs; sh_ks[t] = bk;
            __syncthreads();
            for (int off = 128; off; off >>= 1) {
                if (t < off) {
                    float ov = sh_vs[t + off]; int ok = sh_ks[t + off];
                    if (ov > sh_vs[t] || (ov == sh_vs[t] && ok < sh_ks[t])) { sh_vs[t] = ov; sh_ks[t] = ok; }
                }
                __syncthreads();
            }
            best_k = sh_ks[0];
        }

        if (t == 0) {
            g_idx[n] = best_k;
            atomicAdd(&g_hist[best_k], 1);
            if (write_extras) out[ZQ_ELEMS + 2 + n] = (float)best_k;
        }
    }
}

// ==== Kernel C: coalesced gather + STE write + loss + (last block) scalars ====
__global__ void __launch_bounds__(256) k_out(const float* __restrict__ ze,
                                             const float* __restrict__ w,
                                             float* __restrict__ out,
                                             int write_extras) {
    __shared__ float tile[32][33];
    __shared__ int   kk[32];
    __shared__ float sr[8];
    __shared__ int   s_last;
    int blk = blockIdx.x, t = threadIdx.x;
    int tx = t & 31, ty = t >> 5;
    int b = blk >> 8, rem = blk & 255;
    int d0 = (rem >> 5) << 5;
    int hw0 = (rem & 31) << 5;

    if (t < 32) kk[t] = g_idx[b * HWSZ + hw0 + t];
    __syncthreads();
#pragma unroll
    for (int i = 0; i < 4; i++) {
        int tok = ty + i * 8;
        tile[tok][tx] = __ldg(&w[(size_t)kk[tok] * DIM + d0 + tx]);
    }
    __syncthreads();

    float acc = 0.f;
#pragma unroll
    for (int i = 0; i < 4; i++) {
        int dd = ty + i * 8;
        size_t gi = (size_t)(b * DIM + d0 + dd) * HWSZ + hw0 + tx;  // NCHW, coalesced
        float zq  = tile[tx][dd];
        float zev = ze[gi];
        float df  = zq - zev;
        out[gi]   = zev + df;
        acc += df * df;
    }
#pragma unroll
    for (int o = 16; o; o >>= 1) acc += __shfl_xor_sync(0xffffffffu, acc, o);
    if ((t & 31) == 0) sr[t >> 5] = acc;
    __syncthreads();
    if (t == 0) {
        float tot = 0.f;
#pragma unroll
        for (int q = 0; q < 8; q++) tot += sr[q];
        atomicAdd(&g_loss, (double)tot);
        __threadfence();
        unsigned old = atomicAdd(&g_done, 1u);
        s_last = (old == gridDim.x - 1) ? 1 : 0;
    }
    __syncthreads();

    if (s_last && write_extras) {
        double accp = 0.0;
        for (int k = t; k < KCODES; k += 256) {
            float p = (float)g_hist[k] * (1.0f / (float)NTOK);
            accp += (double)(p * logf(p + 1e-10f));
        }
#pragma unroll
        for (int o = 16; o; o >>= 1) accp += __shfl_xor_sync(0xffffffffu, accp, o);
        __shared__ double dr[8];
        if ((t & 31) == 0) dr[t >> 5] = accp;
        __syncthreads();
        if (t == 0) {
            double tot = 0.0;
#pragma unroll
            for (int q = 0; q < 8; q++) tot += dr[q];
            double loss = *((volatile double*)&g_loss);
            out[ZQ_ELEMS]     = (float)(1.25 * loss / (double)ZQ_ELEMS);
            out[ZQ_ELEMS + 1] = (float)exp(-tot);
        }
    }
}

extern "C" void kernel_launch(void* const* d_in, const int* in_sizes, int n_in,
                              void* d_out, int out_size) {
    const float* gum = nullptr;
    const float* small[2] = {nullptr, nullptr};
    int ns = 0;
    for (int i = 0; i < n_in; i++) {
        if (in_sizes[i] == KCODES * NTOK) gum = (const float*)d_in[i];
        else if (ns < 2) small[ns++] = (const float*)d_in[i];
    }
    const float* z_e = small[0];
    const float* w   = small[1];
    float* out = (float*)d_out;
    int write_extras = (out_size >= OUT_FULL) ? 1 : 0;

    k_prep<<<1568, 256>>>(z_e, w);
    k_argmax<<<NTOK, 256>>>(gum, out, write_extras);
    k_resolve<<<1184, 256>>>(gum, z_e, w, out, write_extras);
    k_out<<<2048, 256>>>(z_e, w, out, write_extras);
}

// round 17
// speedup vs baseline: 1.0629x; 1.0629x over previous
#include <cuda_runtime.h>
#include <math.h>

#define KCODES   8192
#define DIM      256
#define NTOK     8192       // B*H*W
#define HWSZ     1024
#define ZQ_ELEMS 2097152
#define OUT_FULL (ZQ_ELEMS + 2 + NTOK)
#define CAP      256
#define NPART    16         // |z|^2 partials per token

static __device__ float    g_zn2p[NPART * NTOK]; // per-token |z|^2 partials
static __device__ float    g_w2[KCODES];
static __device__ unsigned g_wmax2_bits;         // monotone max, idempotent across replays
static __device__ int      g_idx[NTOK];
static __device__ int      g_hist[KCODES];
static __device__ double   g_loss;
static __device__ unsigned g_done;

// ==== Kernel A: |z|^2 partials (coalesced over NCHW) + |w|^2 + zeroing =======
__global__ void __launch_bounds__(256) k_prep(const float* __restrict__ ze,
                                              const float* __restrict__ w) {
    int blk = blockIdx.x, t = threadIdx.x;
    if (blk < 512) {
        // |z|^2 partial over a 16-d chunk for 256 hw positions; fully coalesced, MLP=16
        int b   = blk >> 6;
        int rem = blk & 63;
        int hwc = rem >> 4;          // 4 hw chunks of 256
        int dc  = rem & 15;          // 16 d chunks of 16
        int hw  = (hwc << 8) + t;
        const float* p = ze + (size_t)(b * DIM + dc * 16) * HWSZ + hw;
        float acc = 0.f;
#pragma unroll
        for (int d = 0; d < 16; d++) {
            float v = __ldg(p + (size_t)d * HWSZ);
            acc += v * v;
        }
        g_zn2p[dc * NTOK + (b << 10) + hw] = acc;
    } else if (blk < 1536) {
        // |w_k|^2 (one warp per row) + block-reduced global max (1 atomic/block)
        __shared__ float wm[8];
        int lane = t & 31, wrp = t >> 5;
        int row  = ((blk - 512) << 3) | wrp;
        const float4* p = (const float4*)(w + (size_t)row * DIM);
        float s = 0.f;
#pragma unroll
        for (int j = 0; j < 2; j++) {
            float4 v = __ldg(p + lane * 2 + j);
            s += v.x * v.x + v.y * v.y + v.z * v.z + v.w * v.w;
        }
#pragma unroll
        for (int o = 16; o; o >>= 1) s += __shfl_xor_sync(0xffffffffu, s, o);
        if (lane == 0) { g_w2[row] = s; wm[wrp] = s; }
        __syncthreads();
        if (t == 0) {
            float mx = wm[0];
#pragma unroll
            for (int q = 1; q < 8; q++) mx = fmaxf(mx, wm[q]);
            atomicMax(&g_wmax2_bits, __float_as_uint(mx));
        }
    } else {
        int i = ((blk - 1536) << 8) | t;
        g_hist[i] = 0;
        if (i == 0) { g_loss = 0.0; g_done = 0u; }
    }
}

// == Kernel B: argmax, single LTS pass + selective per-thread re-read (~2MB) ==
__global__ void __launch_bounds__(256, 7) k_argmax(const float* __restrict__ gum,
                                                   const float* __restrict__ ze,
                                                   const float* __restrict__ w,
                                                   float* __restrict__ out,
                                                   int write_extras) {
    const int n = blockIdx.x;
    const int t = threadIdx.x;
    const int lane = t & 31, wrp = t >> 5;
    const int b = n >> 10, hw = n & (HWSZ - 1);
    __shared__ float sh_z[DIM];
    __shared__ float sh_p[NPART];
    __shared__ int   sh_cand[CAP];
    __shared__ float sh_cg[CAP];
    __shared__ int   sh_cnt;
    __shared__ float sh_red[8];
    __shared__ float sh_bv[8];
    __shared__ int   sh_bk[8];

    if (t < NPART) sh_p[t] = g_zn2p[t * NTOK + n];   // |z|^2 partials
    if (t == 0) sh_cnt = 0;

    // ---- single streaming pass: per-thread running max only (values dead) ----
    const float4* row4 = (const float4*)(gum + (size_t)n * KCODES);
    float mt = -INFINITY;
#pragma unroll
    for (int j = 0; j < 8; j++) {
        float4 v = __ldcs(row4 + t + j * 256);
        mt = fmaxf(mt, fmaxf(fmaxf(v.x, v.y), fmaxf(v.z, v.w)));
    }
    float m = mt;
#pragma unroll
    for (int o = 16; o; o >>= 1) m = fmaxf(m, __shfl_xor_sync(0xffffffffu, m, o));
    if (lane == 0) sh_red[wrp] = m;
    __syncthreads();
    float gmax = sh_red[0];
#pragma unroll
    for (int i = 1; i < 8; i++) gmax = fmaxf(gmax, sh_red[i]);
    float zn2 = 0.f;
#pragma unroll
    for (int i = 0; i < NPART; i++) zn2 += sh_p[i];
    float wmax2  = __uint_as_float(g_wmax2_bits);
    float thresh = gmax - (4.f * sqrtf(zn2) * sqrtf(wmax2) + wmax2 + 1e-5f);

    // ---- selective re-read: only threads whose local max clears the bar ----
    if (mt >= thresh) {
#pragma unroll
        for (int j = 0; j < 8; j++) {
            float4 v = __ldg(row4 + t + j * 256);
            int kb = (t + j * 256) << 2;
            if (v.x >= thresh) { int p = atomicAdd(&sh_cnt, 1); if (p < CAP) { sh_cand[p] = kb;     sh_cg[p] = v.x; } }
            if (v.y >= thresh) { int p = atomicAdd(&sh_cnt, 1); if (p < CAP) { sh_cand[p] = kb + 1; sh_cg[p] = v.y; } }
            if (v.z >= thresh) { int p = atomicAdd(&sh_cnt, 1); if (p < CAP) { sh_cand[p] = kb + 2; sh_cg[p] = v.z; } }
            if (v.w >= thresh) { int p = atomicAdd(&sh_cnt, 1); if (p < CAP) { sh_cand[p] = kb + 3; sh_cg[p] = v.w; } }
        }
    }
    __syncthreads();
    int cnt = sh_cnt;
    int best_k = -1;

    if (cnt == 1) {
        best_k = sh_cand[0];                         // ~87% of tokens: no z needed at all
    } else {
        // lazy scattered z load, only for multi-candidate blocks (~13%)
        sh_z[t] = __ldg(&ze[(size_t)(b * DIM + t) * HWSZ + hw]);
        __syncthreads();
        if (cnt <= CAP) {
            // warp-parallel exact scoring: warp handles candidates wrp, wrp+8, ...
            float bv = -INFINITY; int bk = KCODES;
            for (int c = wrp; c < cnt; c += 8) {
                int k = sh_cand[c];
                const float4* wr = (const float4*)(w + (size_t)k * DIM);
                float dot = 0.f;
#pragma unroll
                for (int j = 0; j < 2; j++) {
                    float4 a = __ldg(wr + lane * 2 + j);
                    int db = lane * 8 + j * 4;
                    dot += a.x * sh_z[db] + a.y * sh_z[db + 1] + a.z * sh_z[db + 2] + a.w * sh_z[db + 3];
                }
#pragma unroll
                for (int o = 16; o; o >>= 1) dot += __shfl_xor_sync(0xffffffffu, dot, o);
                float sc = sh_cg[c] + 2.f * dot - g_w2[k];
                if (sc > bv || (sc == bv && k < bk)) { bv = sc; bk = k; }
            }
            if (lane == 0) { sh_bv[wrp] = bv; sh_bk[wrp] = bk; }
            __syncthreads();
            if (t == 0) {
                float fb = -INFINITY; int fk = KCODES;
#pragma unroll
                for (int i = 0; i < 8; i++) {
                    float v = sh_bv[i]; int k = sh_bk[i];
                    if (v > fb || (v == fb && k < fk)) { fb = v; fk = k; }
                }
                best_k = fk;
            }
        } else {
            // statistically unreachable safety net: exact full scan
            float bs = -INFINITY; int bk = KCODES;
            for (int k = t; k < KCODES; k += 256) {
                float dot = 0.f;
                for (int d = 0; d < DIM; d++) dot += sh_z[d] * w[(size_t)k * DIM + d];
                float sc = __ldg(&gum[(size_t)n * KCODES + k]) + 2.f * dot - g_w2[k];
                if (sc > bs || (sc == bs && k < bk)) { bs = sc; bk = k; }
            }
            __syncthreads();
            sh_cg[t] = bs; sh_cand[t] = bk;
            __syncthreads();
            for (int off = 128; off; off >>= 1) {
                if (t < off) {
                    float ov = sh_cg[t + off]; int ok = sh_cand[t + off];
                    if (ov > sh_cg[t] || (ov == sh_cg[t] && ok < sh_cand[t])) { sh_cg[t] = ov; sh_cand[t] = ok; }
                }
                __syncthreads();
            }
            best_k = sh_cand[0];
        }
    }

    if (t == 0) {
        g_idx[n] = best_k;
        atomicAdd(&g_hist[best_k], 1);
        if (write_extras) out[ZQ_ELEMS + 2 + n] = (float)best_k;
    }
}

// == Kernel C: vectorized gather + STE write + loss; 128hw x 32d tiles ========
__global__ void __launch_bounds__(256) k_out(const float* __restrict__ ze,
                                             const float* __restrict__ w,
                                             float* __restrict__ out,
                                             int write_extras) {
    __shared__ float tile[32][132];    // [dim-local][token]; 132-pad: 16B-aligned rows
    __shared__ int   kk[128];
    __shared__ float sr[8];
    __shared__ int   s_last;
    int blk = blockIdx.x, t = threadIdx.x;
    int b = blk >> 6, rem = blk & 63;
    int d0  = (rem >> 3) << 5;        // 8 d-chunks of 32
    int hw0 = (rem & 7) << 7;         // 8 hw-chunks of 128

    if (t < 128) kk[t] = g_idx[b * HWSZ + hw0 + t];
    __syncthreads();

    // gather 128 codebook row-slices (32 dims each): 2 threads/row, 4x LDG.128 each
    {
        int r = t >> 1, half = t & 1;
        const float4* wr = (const float4*)(w + (size_t)kk[r] * DIM + d0 + half * 16);
#pragma unroll
        for (int j = 0; j < 4; j++) {
            float4 v = __ldg(wr + j);
            int dl = half * 16 + j * 4;
            tile[dl + 0][r] = v.x;
            tile[dl + 1][r] = v.y;
            tile[dl + 2][r] = v.z;
            tile[dl + 3][r] = v.w;
        }
    }
    __syncthreads();

    // main: LDS.128 + LDG.128 + STG.128 per iteration, fully coalesced NCHW
    int tx = t & 31, ty = t >> 5;
    float acc = 0.f;
#pragma unroll
    for (int i = 0; i < 4; i++) {
        int dd = ty + i * 8;
        size_t gi = ((size_t)(b * DIM + d0 + dd) * HWSZ + hw0 + tx * 4);
        float4 zq  = *(const float4*)&tile[dd][tx * 4];
        float4 zev = *(const float4*)&ze[gi];
        float4 o;
        float dx = zq.x - zev.x, dy = zq.y - zev.y, dz = zq.z - zev.z, dw = zq.w - zev.w;
        o.x = zev.x + dx; o.y = zev.y + dy; o.z = zev.z + dz; o.w = zev.w + dw;
        *(float4*)&out[gi] = o;
        acc += dx * dx + dy * dy + dz * dz + dw * dw;
    }
#pragma unroll
    for (int o = 16; o; o >>= 1) acc += __shfl_xor_sync(0xffffffffu, acc, o);
    if (tx == 0) sr[ty] = acc;
    __syncthreads();
    if (t == 0) {
        float tot = 0.f;
#pragma unroll
        for (int q = 0; q < 8; q++) tot += sr[q];
        atomicAdd(&g_loss, (double)tot);
        __threadfence();
        unsigned old = atomicAdd(&g_done, 1u);
        s_last = (old == gridDim.x - 1) ? 1 : 0;
    }
    __syncthreads();

    if (s_last && write_extras) {
        double accp = 0.0;
        for (int k = t; k < KCODES; k += 256) {
            float p = (float)g_hist[k] * (1.0f / (float)NTOK);
            accp += (double)(p * logf(p + 1e-10f));
        }
#pragma unroll
        for (int o = 16; o; o >>= 1) accp += __shfl_xor_sync(0xffffffffu, accp, o);
        __shared__ double dr[8];
        if ((t & 31) == 0) dr[t >> 5] = accp;
        __syncthreads();
        if (t == 0) {
            double tot = 0.0;
#pragma unroll
            for (int q = 0; q < 8; q++) tot += dr[q];
            double loss = *((volatile double*)&g_loss);
            out[ZQ_ELEMS]     = (float)(1.25 * loss / (double)ZQ_ELEMS);
            out[ZQ_ELEMS + 1] = (float)exp(-tot);
        }
    }
}

extern "C" void kernel_launch(void* const* d_in, const int* in_sizes, int n_in,
                              void* d_out, int out_size) {
    const float* gum = nullptr;
    const float* small[2] = {nullptr, nullptr};
    int ns = 0;
    for (int i = 0; i < n_in; i++) {
        if (in_sizes[i] == KCODES * NTOK) gum = (const float*)d_in[i];
        else if (ns < 2) small[ns++] = (const float*)d_in[i];
    }
    const float* z_e = small[0];
    const float* w   = small[1];
    float* out = (float*)d_out;
    int write_extras = (out_size >= OUT_FULL) ? 1 : 0;

    k_prep<<<1568, 256>>>(z_e, w);
    k_argmax<<<NTOK, 256>>>(gum, z_e, w, out, write_extras);
    k_out<<<512, 256>>>(z_e, w, out, write_extras);
}